// round 1
// baseline (speedup 1.0000x reference)
#include <cuda_runtime.h>
#include <math.h>

#define N_NODES 4096
#define N_EDGES 131072
#define IN_CH   128
#define H       256
#define NCLS    16
#define NHEAD   4
#define HD      64
#define KSPLIT  4
#define EPS     1e-5f

// ---------------- device scratch (static, no allocs) ----------------
__device__ float g_deg[N_NODES];
__device__ float g_dinv[N_NODES];
__device__ int   g_cnt[N_NODES];
__device__ int   g_rowptr[N_NODES + 1];
__device__ int   g_cursor[N_NODES];
__device__ int   g_eidx[N_EDGES];

__device__ __align__(16) float g_h   [N_NODES * H];       // gemm scratch
__device__ __align__(16) float g_g1  [N_NODES * H];       // gcn1 out (relu)
__device__ __align__(16) float g_xl  [N_NODES * H];       // x_local
__device__ __align__(16) float g_qkv [N_NODES * 3 * H];
__device__ __align__(16) float g_ctx [N_NODES * H];
__device__ __align__(16) float g_x1  [N_NODES * H];       // after ln1
__device__ __align__(16) float g_ffn [N_NODES * 4 * H];
__device__ __align__(16) float g_f2  [N_NODES * H];
__device__ __align__(16) float g_xf  [N_NODES * H];       // x_final
__device__ __align__(16) float g_d1  [N_NODES * 2 * H];
__device__ __align__(16) float g_pacc[NHEAD * KSPLIT * N_NODES * HD];
__device__ float g_pm[NHEAD * KSPLIT * N_NODES];
__device__ float g_pl[NHEAD * KSPLIT * N_NODES];

// ---------------- small kernels ----------------
__global__ void k_zero() {
    int i = blockIdx.x * blockDim.x + threadIdx.x;
    if (i < N_NODES) { g_deg[i] = 0.f; g_cnt[i] = 0; }
}

__global__ void k_deg(const int* __restrict__ ei, const float* __restrict__ ew) {
    int e = blockIdx.x * blockDim.x + threadIdx.x;
    if (e < N_EDGES) {
        int d = ei[N_EDGES + e];
        atomicAdd(&g_deg[d], ew[e]);
        atomicAdd(&g_cnt[d], 1);
    }
}

__global__ void k_dinv() {
    int i = blockIdx.x * blockDim.x + threadIdx.x;
    if (i < N_NODES) g_dinv[i] = rsqrtf(g_deg[i] + 1.0f);  // self-loop weight 1
}

// exclusive scan of g_cnt -> g_rowptr / g_cursor (single block, 1024 threads)
__global__ void k_scan() {
    __shared__ int wsum[32];
    int t = threadIdx.x;
    int base = t * 4;
    int v[4];
#pragma unroll
    for (int i = 0; i < 4; i++) v[i] = g_cnt[base + i];
    int tot = v[0] + v[1] + v[2] + v[3];
    int lane = t & 31, w = t >> 5;
    int x = tot;
#pragma unroll
    for (int o = 1; o < 32; o <<= 1) {
        int y = __shfl_up_sync(0xffffffffu, x, o);
        if (lane >= o) x += y;
    }
    if (lane == 31) wsum[w] = x;
    __syncthreads();
    if (w == 0) {
        int y = wsum[lane];
#pragma unroll
        for (int o = 1; o < 32; o <<= 1) {
            int z = __shfl_up_sync(0xffffffffu, y, o);
            if (lane >= o) y += z;
        }
        wsum[lane] = y;
    }
    __syncthreads();
    int wbase = (w > 0) ? wsum[w - 1] : 0;
    int run = wbase + x - tot;   // exclusive prefix
#pragma unroll
    for (int i = 0; i < 4; i++) {
        g_rowptr[base + i] = run;
        g_cursor[base + i] = run;
        run += v[i];
    }
    if (t == 1023) g_rowptr[N_NODES] = run;
}

__global__ void k_fill(const int* __restrict__ ei) {
    int e = blockIdx.x * blockDim.x + threadIdx.x;
    if (e < N_EDGES) {
        int d = ei[N_EDGES + e];
        int p = atomicAdd(&g_cursor[d], 1);
        g_eidx[p] = e;
    }
}

// GCN aggregation: out[n,c] = dinv[n]^2*h[n,c] + sum_e dinv[src]*ew*dinv[n]*h[src,c] + bias[c]
__global__ void k_gather(const float* __restrict__ h, const int* __restrict__ ei,
                         const float* __restrict__ ew, const float* __restrict__ bias,
                         float* __restrict__ out, int relu) {
    int n = blockIdx.x;
    int c = threadIdx.x;  // 256
    int beg = g_rowptr[n], end = g_rowptr[n + 1];
    float dn = g_dinv[n];
    float acc = dn * dn * h[n * H + c];
    __shared__ int   ssrc[64];
    __shared__ float scoef[64];
    for (int b0 = beg; b0 < end; b0 += 64) {
        int cnt = min(64, end - b0);
        if (c < cnt) {
            int e = g_eidx[b0 + c];
            int s = ei[e];  // src row
            ssrc[c] = s;
            scoef[c] = g_dinv[s] * ew[e] * dn;
        }
        __syncthreads();
        for (int i = 0; i < cnt; i++)
            acc += scoef[i] * h[ssrc[i] * H + c];
        __syncthreads();
    }
    float v = acc + bias[c];
    out[n * H + c] = relu ? fmaxf(v, 0.f) : v;
}

// ---------------- SGEMM: C[M,N] = A[M,K] @ B (+bias)(+relu) ----------------
// BT=false: B is [K,N] row-major.  BT=true: B is [N,K] row-major (C = A @ B^T).
template <bool BT, int ACT>
__global__ void __launch_bounds__(256) k_gemm(const float* __restrict__ A,
                                              const float* __restrict__ B,
                                              const float* __restrict__ bias,
                                              float* __restrict__ C,
                                              int M, int Nn, int K) {
    const int BM = 64, BN = 64, BK = 16;
    __shared__ float As[BK][BM + 4];
    __shared__ float Bs[BK][BN + 4];
    int tid = threadIdx.x;
    int tx = tid & 15, ty = tid >> 4;
    int m0 = blockIdx.y * BM, n0 = blockIdx.x * BN;
    float acc[4][4] = {};
    for (int k0 = 0; k0 < K; k0 += BK) {
#pragma unroll
        for (int i = 0; i < 4; i++) {
            int lin = tid + i * 256;
            int m = lin >> 4, kk = lin & 15;
            As[kk][m] = A[(size_t)(m0 + m) * K + k0 + kk];
        }
        if (BT) {
#pragma unroll
            for (int i = 0; i < 4; i++) {
                int lin = tid + i * 256;
                int n = lin >> 4, kk = lin & 15;
                Bs[kk][n] = B[(size_t)(n0 + n) * K + k0 + kk];
            }
        } else {
#pragma unroll
            for (int i = 0; i < 4; i++) {
                int lin = tid + i * 256;
                int kk = lin >> 6, n = lin & 63;
                Bs[kk][n] = B[(size_t)(k0 + kk) * Nn + n0 + n];
            }
        }
        __syncthreads();
#pragma unroll
        for (int kk = 0; kk < BK; kk++) {
            float4 av = *(const float4*)&As[kk][ty * 4];
            float4 bv = *(const float4*)&Bs[kk][tx * 4];
            float a[4] = {av.x, av.y, av.z, av.w};
            float b[4] = {bv.x, bv.y, bv.z, bv.w};
#pragma unroll
            for (int i = 0; i < 4; i++)
#pragma unroll
                for (int j = 0; j < 4; j++)
                    acc[i][j] += a[i] * b[j];
        }
        __syncthreads();
    }
#pragma unroll
    for (int i = 0; i < 4; i++) {
        int m = m0 + ty * 4 + i;
#pragma unroll
        for (int j = 0; j < 4; j++) {
            int n = n0 + tx * 4 + j;
            float v = acc[i][j];
            if (bias) v += bias[n];
            if (ACT == 1) v = fmaxf(v, 0.f);
            C[(size_t)m * Nn + n] = v;
        }
    }
}

// ---------------- attention: split-K flash, per-thread query ----------------
__global__ void __launch_bounds__(128) k_attn(const float* __restrict__ qkv) {
    int head = blockIdx.y;
    int z = blockIdx.z;
    int t = threadIdx.x;
    int qi = blockIdx.x * 128 + t;
    const int KB = N_NODES / KSPLIT;  // 1024
    int kbeg = z * KB;

    const float4* qkv4 = (const float4*)qkv;
    float q[HD];
    {
        size_t qb = (size_t)qi * 192 + head * 16;  // q offset, float4 units
#pragma unroll
        for (int c4 = 0; c4 < 16; c4++) {
            float4 v = qkv4[qb + c4];
            q[4 * c4 + 0] = v.x * 0.125f;
            q[4 * c4 + 1] = v.y * 0.125f;
            q[4 * c4 + 2] = v.z * 0.125f;
            q[4 * c4 + 3] = v.w * 0.125f;
        }
    }
    float acc[HD];
#pragma unroll
    for (int d = 0; d < HD; d++) acc[d] = 0.f;
    float m = -1e30f, l = 0.f;

    __shared__ float4 Ks[16 * 16];
    __shared__ float4 Vs[16 * 16];

    for (int k0 = kbeg; k0 < kbeg + KB; k0 += 16) {
        __syncthreads();
#pragma unroll
        for (int i = 0; i < 2; i++) {
            int lin = t + i * 128;      // 0..255
            int row = lin >> 4, col = lin & 15;
            size_t rb = (size_t)(k0 + row) * 192;
            Ks[lin] = qkv4[rb + 64 + head * 16 + col];   // K
            Vs[lin] = qkv4[rb + 128 + head * 16 + col];  // V
        }
        __syncthreads();

        float s[16];
#pragma unroll
        for (int j = 0; j < 16; j++) {
            float s0 = 0.f, s1 = 0.f, s2 = 0.f, s3 = 0.f;
#pragma unroll
            for (int c4 = 0; c4 < 16; c4++) {
                float4 kk = Ks[j * 16 + c4];
                s0 += q[4 * c4 + 0] * kk.x;
                s1 += q[4 * c4 + 1] * kk.y;
                s2 += q[4 * c4 + 2] * kk.z;
                s3 += q[4 * c4 + 3] * kk.w;
            }
            s[j] = (s0 + s1) + (s2 + s3);
        }
        float tm = s[0];
#pragma unroll
        for (int j = 1; j < 16; j++) tm = fmaxf(tm, s[j]);
        float mn = fmaxf(m, tm);
        float corr = __expf(m - mn);
        l *= corr;
#pragma unroll
        for (int d = 0; d < HD; d++) acc[d] *= corr;
#pragma unroll
        for (int j = 0; j < 16; j++) {
            float p = __expf(s[j] - mn);
            l += p;
#pragma unroll
            for (int c4 = 0; c4 < 16; c4++) {
                float4 vv = Vs[j * 16 + c4];
                acc[4 * c4 + 0] += p * vv.x;
                acc[4 * c4 + 1] += p * vv.y;
                acc[4 * c4 + 2] += p * vv.z;
                acc[4 * c4 + 3] += p * vv.w;
            }
        }
        m = mn;
    }
    int idx = (head * KSPLIT + z) * N_NODES + qi;
    float* pa = g_pacc + (size_t)idx * HD;
#pragma unroll
    for (int d = 0; d < HD; d++) pa[d] = acc[d];
    g_pm[idx] = m;
    g_pl[idx] = l;
}

__global__ void k_merge(float* __restrict__ ctx) {
    int gid = blockIdx.x * blockDim.x + threadIdx.x;  // NHEAD*N*HD
    int d = gid & (HD - 1);
    int n = (gid >> 6) & (N_NODES - 1);
    int head = gid >> 18;
    float M = -1e30f;
#pragma unroll
    for (int z = 0; z < KSPLIT; z++)
        M = fmaxf(M, g_pm[(head * KSPLIT + z) * N_NODES + n]);
    float num = 0.f, den = 0.f;
#pragma unroll
    for (int z = 0; z < KSPLIT; z++) {
        int idx = (head * KSPLIT + z) * N_NODES + n;
        float w = __expf(g_pm[idx] - M);
        num += w * g_pacc[(size_t)idx * HD + d];
        den += w * g_pl[idx];
    }
    ctx[n * H + head * HD + d] = num / den;
}

// out = (res ? res : 0) + LayerNorm(a + b) * g + beta
__global__ void k_ln(const float* __restrict__ a, const float* __restrict__ bb,
                     const float* __restrict__ g, const float* __restrict__ beta,
                     const float* __restrict__ res, float* __restrict__ out) {
    int n = blockIdx.x, t = threadIdx.x;  // 256
    float v = a[n * H + t] + bb[n * H + t];
    __shared__ float red[8];
    float s = v;
#pragma unroll
    for (int o = 16; o; o >>= 1) s += __shfl_xor_sync(0xffffffffu, s, o);
    if ((t & 31) == 0) red[t >> 5] = s;
    __syncthreads();
    float tot = 0.f;
#pragma unroll
    for (int i = 0; i < 8; i++) tot += red[i];
    float mean = tot * (1.f / H);
    float d = v - mean;
    float s2 = d * d;
#pragma unroll
    for (int o = 16; o; o >>= 1) s2 += __shfl_xor_sync(0xffffffffu, s2, o);
    __syncthreads();
    if ((t & 31) == 0) red[t >> 5] = s2;
    __syncthreads();
    float tot2 = 0.f;
#pragma unroll
    for (int i = 0; i < 8; i++) tot2 += red[i];
    float var = tot2 * (1.f / H);
    float o_ = d * rsqrtf(var + EPS) * g[t] + beta[t];
    if (res) o_ += res[n * H + t];
    out[n * H + t] = o_;
}

// classifier head + log_softmax (warp per row)
__global__ void k_cls(const float* __restrict__ xf, const float* __restrict__ W,
                      const float* __restrict__ b, float* __restrict__ out) {
    int n = blockIdx.x;
    int lane = threadIdx.x;  // 32
    float acc = -1e30f;
    if (lane < NCLS) {
        const float* xr = xf + (size_t)n * H;
        float a = 0.f;
        for (int k = 0; k < H; k++) a += xr[k] * W[k * NCLS + lane];
        acc = a + b[lane];
    }
    float mx = acc;
#pragma unroll
    for (int o = 8; o; o >>= 1) mx = fmaxf(mx, __shfl_xor_sync(0xffffffffu, mx, o, 16));
    float e = (lane < NCLS) ? __expf(acc - mx) : 0.f;
    float se = e;
#pragma unroll
    for (int o = 8; o; o >>= 1) se += __shfl_xor_sync(0xffffffffu, se, o, 16);
    if (lane < NCLS) out[n * NCLS + lane] = acc - mx - logf(se);
}

// decoder second layer + sigmoid (warp per row)
__global__ void k_d2(const float* __restrict__ d1, const float* __restrict__ W,
                     const float* __restrict__ b, float* __restrict__ out) {
    int n = blockIdx.x;
    int lane = threadIdx.x;
    const float* xr = d1 + (size_t)n * (2 * H);
    float a0 = 0.f, a1 = 0.f, a2 = 0.f;
    for (int k = lane; k < 2 * H; k += 32) {
        float xv = xr[k];
        a0 += xv * W[k * 3 + 0];
        a1 += xv * W[k * 3 + 1];
        a2 += xv * W[k * 3 + 2];
    }
#pragma unroll
    for (int o = 16; o; o >>= 1) {
        a0 += __shfl_xor_sync(0xffffffffu, a0, o);
        a1 += __shfl_xor_sync(0xffffffffu, a1, o);
        a2 += __shfl_xor_sync(0xffffffffu, a2, o);
    }
    if (lane == 0) {
        out[n * 3 + 0] = 1.f / (1.f + __expf(-(a0 + b[0])));
        out[n * 3 + 1] = 1.f / (1.f + __expf(-(a1 + b[1])));
        out[n * 3 + 2] = 1.f / (1.f + __expf(-(a2 + b[2])));
    }
}

// ---------------- launch ----------------
static float* symf(const void* sym) {
    void* p = nullptr;
    cudaGetSymbolAddress(&p, sym);
    return (float*)p;
}

extern "C" void kernel_launch(void* const* d_in, const int* in_sizes, int n_in,
                              void* d_out, int out_size) {
    const float* x        = (const float*)d_in[0];
    const int*   ei       = (const int*)d_in[1];
    const float* ea       = (const float*)d_in[2];
    const float* W_gcn1   = (const float*)d_in[3];
    const float* b_gcn1   = (const float*)d_in[4];
    const float* W_gcn2   = (const float*)d_in[5];
    const float* b_gcn2   = (const float*)d_in[6];
    const float* in_proj_w  = (const float*)d_in[7];
    const float* in_proj_b  = (const float*)d_in[8];
    const float* out_proj_w = (const float*)d_in[9];
    const float* out_proj_b = (const float*)d_in[10];
    const float* ln1_g    = (const float*)d_in[11];
    const float* ln1_b    = (const float*)d_in[12];
    const float* ffn_w1   = (const float*)d_in[13];
    const float* ffn_b1   = (const float*)d_in[14];
    const float* ffn_w2   = (const float*)d_in[15];
    const float* ffn_b2   = (const float*)d_in[16];
    const float* ln2_g    = (const float*)d_in[17];
    const float* ln2_b    = (const float*)d_in[18];
    const float* W_cls    = (const float*)d_in[19];
    const float* b_cls    = (const float*)d_in[20];
    const float* W_d1     = (const float*)d_in[21];
    const float* b_d1     = (const float*)d_in[22];
    const float* W_d2     = (const float*)d_in[23];
    const float* b_d2     = (const float*)d_in[24];

    float* out_cls  = (float*)d_out;
    float* out_reco = out_cls + (size_t)N_NODES * NCLS;

    float* p_h   = symf(g_h);
    float* p_g1  = symf(g_g1);
    float* p_xl  = symf(g_xl);
    float* p_qkv = symf(g_qkv);
    float* p_ctx = symf(g_ctx);
    float* p_x1  = symf(g_x1);
    float* p_ffn = symf(g_ffn);
    float* p_f2  = symf(g_f2);
    float* p_xf  = symf(g_xf);
    float* p_d1  = symf(g_d1);

    // graph structure
    k_zero<<<N_NODES / 256, 256>>>();
    k_deg<<<N_EDGES / 256, 256>>>(ei, ea);
    k_dinv<<<N_NODES / 256, 256>>>();
    k_scan<<<1, 1024>>>();
    k_fill<<<N_EDGES / 256, 256>>>(ei);

    // GCN layer 1: h = x @ W1 ; gather ; +b ; relu
    k_gemm<false, 0><<<dim3(H / 64, N_NODES / 64), 256>>>(x, W_gcn1, nullptr, p_h,
                                                          N_NODES, H, IN_CH);
    k_gather<<<N_NODES, H>>>(p_h, ei, ea, b_gcn1, p_g1, 1);

    // GCN layer 2
    k_gemm<false, 0><<<dim3(H / 64, N_NODES / 64), 256>>>(p_g1, W_gcn2, nullptr, p_h,
                                                          N_NODES, H, H);
    k_gather<<<N_NODES, H>>>(p_h, ei, ea, b_gcn2, p_xl, 0);

    // QKV projection (B transposed)
    k_gemm<true, 0><<<dim3(3 * H / 64, N_NODES / 64), 256>>>(p_xl, in_proj_w, in_proj_b,
                                                             p_qkv, N_NODES, 3 * H, H);

    // attention
    k_attn<<<dim3(N_NODES / 128, NHEAD, KSPLIT), 128>>>(p_qkv);
    k_merge<<<(NHEAD * N_NODES * HD) / 256, 256>>>(p_ctx);

    // out projection (B transposed)
    k_gemm<true, 0><<<dim3(H / 64, N_NODES / 64), 256>>>(p_ctx, out_proj_w, out_proj_b,
                                                         p_h, N_NODES, H, H);

    // x1 = LN(x_local + attn_out)
    k_ln<<<N_NODES, H>>>(p_xl, p_h, ln1_g, ln1_b, nullptr, p_x1);

    // FFN
    k_gemm<false, 1><<<dim3(4 * H / 64, N_NODES / 64), 256>>>(p_x1, ffn_w1, ffn_b1,
                                                              p_ffn, N_NODES, 4 * H, H);
    k_gemm<false, 0><<<dim3(H / 64, N_NODES / 64), 256>>>(p_ffn, ffn_w2, ffn_b2,
                                                          p_f2, N_NODES, H, 4 * H);

    // x_final = x_local + LN(x1 + ffn_out)
    k_ln<<<N_NODES, H>>>(p_x1, p_f2, ln2_g, ln2_b, p_xl, p_xf);

    // heads
    k_cls<<<N_NODES, 32>>>(p_xf, W_cls, b_cls, out_cls);
    k_gemm<false, 1><<<dim3(2 * H / 64, N_NODES / 64), 256>>>(p_xf, W_d1, b_d1,
                                                              p_d1, N_NODES, 2 * H, H);
    k_d2<<<N_NODES, 32>>>(p_d1, W_d2, b_d2, out_reco);
}

// round 2
// speedup vs baseline: 2.3507x; 2.3507x over previous
#include <cuda_runtime.h>
#include <cuda_bf16.h>
#include <math.h>

#define N_NODES 4096
#define N_EDGES 131072
#define IN_CH   128
#define H       256
#define NCLS    16
#define NHEAD   4
#define HD      64
#define KSPLIT  2
#define EPS     1e-5f

// ---------------- device scratch (static, no allocs) ----------------
__device__ float g_deg[N_NODES];
__device__ float g_dinv[N_NODES];
__device__ int   g_cnt[N_NODES];
__device__ int   g_rowptr[N_NODES + 1];
__device__ int   g_cursor[N_NODES];
__device__ int   g_eidx[N_EDGES];

__device__ __align__(16) float g_h   [N_NODES * H];       // gemm scratch
__device__ __align__(16) float g_g1  [N_NODES * H];       // gcn1 out (relu)
__device__ __align__(16) float g_xl  [N_NODES * H];       // x_local
__device__ __align__(16) float g_qkv [N_NODES * 3 * H];
__device__ __align__(16) __nv_bfloat16 g_qkvb[N_NODES * 3 * H];  // bf16 QKV (Q pre-scaled)
__device__ __align__(16) float g_ctx [N_NODES * H];
__device__ __align__(16) float g_x1  [N_NODES * H];       // after ln1
__device__ __align__(16) float g_ffn [N_NODES * 4 * H];
__device__ __align__(16) float g_f2  [N_NODES * H];
__device__ __align__(16) float g_xf  [N_NODES * H];       // x_final
__device__ __align__(16) float g_d1  [N_NODES * 2 * H];
__device__ __align__(16) float g_pacc[NHEAD * KSPLIT * N_NODES * HD];
__device__ float g_pm[NHEAD * KSPLIT * N_NODES];
__device__ float g_pl[NHEAD * KSPLIT * N_NODES];

// ---------------- mma helpers ----------------
__device__ __forceinline__ unsigned sptr(const void* p) {
    return (unsigned)__cvta_generic_to_shared(p);
}
__device__ __forceinline__ void ldm4(unsigned& r0, unsigned& r1, unsigned& r2, unsigned& r3,
                                     unsigned addr) {
    asm volatile("ldmatrix.sync.aligned.m8n8.x4.shared.b16 {%0,%1,%2,%3},[%4];"
                 : "=r"(r0), "=r"(r1), "=r"(r2), "=r"(r3) : "r"(addr));
}
__device__ __forceinline__ void ldm4t(unsigned& r0, unsigned& r1, unsigned& r2, unsigned& r3,
                                      unsigned addr) {
    asm volatile("ldmatrix.sync.aligned.m8n8.x4.trans.shared.b16 {%0,%1,%2,%3},[%4];"
                 : "=r"(r0), "=r"(r1), "=r"(r2), "=r"(r3) : "r"(addr));
}
__device__ __forceinline__ void mma_bf16(float* d, const unsigned* a, const unsigned* b) {
    asm volatile("mma.sync.aligned.m16n8k16.row.col.f32.bf16.bf16.f32 "
                 "{%0,%1,%2,%3},{%4,%5,%6,%7},{%8,%9},{%0,%1,%2,%3};"
                 : "+f"(d[0]), "+f"(d[1]), "+f"(d[2]), "+f"(d[3])
                 : "r"(a[0]), "r"(a[1]), "r"(a[2]), "r"(a[3]), "r"(b[0]), "r"(b[1]));
}
__device__ __forceinline__ unsigned packbf(float lo, float hi) {
    unsigned r;
    asm("cvt.rn.bf16x2.f32 %0, %1, %2;" : "=r"(r) : "f"(hi), "f"(lo));
    return r;
}

// ---------------- small kernels ----------------
__global__ void k_zero() {
    int i = blockIdx.x * blockDim.x + threadIdx.x;
    if (i < N_NODES) { g_deg[i] = 0.f; g_cnt[i] = 0; }
}

__global__ void k_deg(const int* __restrict__ ei, const float* __restrict__ ew) {
    int e = blockIdx.x * blockDim.x + threadIdx.x;
    if (e < N_EDGES) {
        int d = ei[N_EDGES + e];
        atomicAdd(&g_deg[d], ew[e]);
        atomicAdd(&g_cnt[d], 1);
    }
}

__global__ void k_dinv() {
    int i = blockIdx.x * blockDim.x + threadIdx.x;
    if (i < N_NODES) g_dinv[i] = rsqrtf(g_deg[i] + 1.0f);  // self-loop weight 1
}

// exclusive scan of g_cnt -> g_rowptr / g_cursor (single block, 1024 threads)
__global__ void k_scan() {
    __shared__ int wsum[32];
    int t = threadIdx.x;
    int base = t * 4;
    int v[4];
#pragma unroll
    for (int i = 0; i < 4; i++) v[i] = g_cnt[base + i];
    int tot = v[0] + v[1] + v[2] + v[3];
    int lane = t & 31, w = t >> 5;
    int x = tot;
#pragma unroll
    for (int o = 1; o < 32; o <<= 1) {
        int y = __shfl_up_sync(0xffffffffu, x, o);
        if (lane >= o) x += y;
    }
    if (lane == 31) wsum[w] = x;
    __syncthreads();
    if (w == 0) {
        int y = wsum[lane];
#pragma unroll
        for (int o = 1; o < 32; o <<= 1) {
            int z = __shfl_up_sync(0xffffffffu, y, o);
            if (lane >= o) y += z;
        }
        wsum[lane] = y;
    }
    __syncthreads();
    int wbase = (w > 0) ? wsum[w - 1] : 0;
    int run = wbase + x - tot;   // exclusive prefix
#pragma unroll
    for (int i = 0; i < 4; i++) {
        g_rowptr[base + i] = run;
        g_cursor[base + i] = run;
        run += v[i];
    }
    if (t == 1023) g_rowptr[N_NODES] = run;
}

__global__ void k_fill(const int* __restrict__ ei) {
    int e = blockIdx.x * blockDim.x + threadIdx.x;
    if (e < N_EDGES) {
        int d = ei[N_EDGES + e];
        int p = atomicAdd(&g_cursor[d], 1);
        g_eidx[p] = e;
    }
}

// GCN aggregation
__global__ void k_gather(const float* __restrict__ h, const int* __restrict__ ei,
                         const float* __restrict__ ew, const float* __restrict__ bias,
                         float* __restrict__ out, int relu) {
    int n = blockIdx.x;
    int c = threadIdx.x;  // 256
    int beg = g_rowptr[n], end = g_rowptr[n + 1];
    float dn = g_dinv[n];
    float acc = dn * dn * h[n * H + c];
    __shared__ int   ssrc[64];
    __shared__ float scoef[64];
    for (int b0 = beg; b0 < end; b0 += 64) {
        int cnt = min(64, end - b0);
        if (c < cnt) {
            int e = g_eidx[b0 + c];
            int s = ei[e];
            ssrc[c] = s;
            scoef[c] = g_dinv[s] * ew[e] * dn;
        }
        __syncthreads();
        for (int i = 0; i < cnt; i++)
            acc += scoef[i] * h[ssrc[i] * H + c];
        __syncthreads();
    }
    float v = acc + bias[c];
    out[n * H + c] = relu ? fmaxf(v, 0.f) : v;
}

// ---------------- fp32 SGEMM ----------------
template <bool BT, int ACT>
__global__ void __launch_bounds__(256) k_gemm(const float* __restrict__ A,
                                              const float* __restrict__ B,
                                              const float* __restrict__ bias,
                                              float* __restrict__ C,
                                              int M, int Nn, int K) {
    const int BM = 64, BN = 64, BK = 16;
    __shared__ float As[BK][BM + 4];
    __shared__ float Bs[BK][BN + 4];
    int tid = threadIdx.x;
    int tx = tid & 15, ty = tid >> 4;
    int m0 = blockIdx.y * BM, n0 = blockIdx.x * BN;
    float acc[4][4] = {};
    for (int k0 = 0; k0 < K; k0 += BK) {
#pragma unroll
        for (int i = 0; i < 4; i++) {
            int lin = tid + i * 256;
            int m = lin >> 4, kk = lin & 15;
            As[kk][m] = A[(size_t)(m0 + m) * K + k0 + kk];
        }
        if (BT) {
#pragma unroll
            for (int i = 0; i < 4; i++) {
                int lin = tid + i * 256;
                int n = lin >> 4, kk = lin & 15;
                Bs[kk][n] = B[(size_t)(n0 + n) * K + k0 + kk];
            }
        } else {
#pragma unroll
            for (int i = 0; i < 4; i++) {
                int lin = tid + i * 256;
                int kk = lin >> 6, n = lin & 63;
                Bs[kk][n] = B[(size_t)(k0 + kk) * Nn + n0 + n];
            }
        }
        __syncthreads();
#pragma unroll
        for (int kk = 0; kk < BK; kk++) {
            float4 av = *(const float4*)&As[kk][ty * 4];
            float4 bv = *(const float4*)&Bs[kk][tx * 4];
            float a[4] = {av.x, av.y, av.z, av.w};
            float b[4] = {bv.x, bv.y, bv.z, bv.w};
#pragma unroll
            for (int i = 0; i < 4; i++)
#pragma unroll
                for (int j = 0; j < 4; j++)
                    acc[i][j] += a[i] * b[j];
        }
        __syncthreads();
    }
#pragma unroll
    for (int i = 0; i < 4; i++) {
        int m = m0 + ty * 4 + i;
#pragma unroll
        for (int j = 0; j < 4; j++) {
            int n = n0 + tx * 4 + j;
            float v = acc[i][j];
            if (bias) v += bias[n];
            if (ACT == 1) v = fmaxf(v, 0.f);
            C[(size_t)m * Nn + n] = v;
        }
    }
}

// ---------------- QKV fp32 -> bf16 (Q pre-scaled by 1/sqrt(HD)) ----------------
__global__ void k_cvt_qkv(const float* __restrict__ qkv, __nv_bfloat16* __restrict__ out) {
    int i = blockIdx.x * blockDim.x + threadIdx.x;
    float v = qkv[i];
    int col = i % (3 * H);
    if (col < H) v *= 0.125f;  // 1/sqrt(64)
    out[i] = __float2bfloat16(v);
}

// ---------------- attention: bf16 mma flash, 64q x 64k tiles ----------------
__global__ void __launch_bounds__(128) k_attn_mma(const __nv_bfloat16* __restrict__ qkvb) {
    __shared__ __align__(16) __nv_bfloat16 Qs[64 * 64];
    __shared__ __align__(16) __nv_bfloat16 Ks[64 * 64];
    __shared__ __align__(16) __nv_bfloat16 Vs[64 * 64];
    const int head = blockIdx.y, z = blockIdx.z;
    const int q0 = blockIdx.x * 64;
    const int t = threadIdx.x, w = t >> 5, lane = t & 31;
    const int r_in = lane & 7, mq = lane >> 3;

    // stage Q tile (rows q0..q0+63, head slice), XOR-swizzled per row
    {
        int r = t >> 1, cb = (t & 1) * 4;
        const uint4* src = (const uint4*)(qkvb + (size_t)(q0 + r) * 768 + head * 64);
        uint4* dst = (uint4*)(Qs + r * 64);
#pragma unroll
        for (int i = 0; i < 4; i++) { int c = cb + i; dst[c ^ (r & 7)] = src[c]; }
    }
    __syncthreads();

    // Q A-fragments: warp rows 16w..16w+15, 4 k16 steps over HD
    unsigned qf[4][4];
    {
        int row = 16 * w + (mq & 1) * 8 + r_in;
#pragma unroll
        for (int kk = 0; kk < 4; kk++) {
            int ch = 2 * kk + (mq >> 1);
            ldm4(qf[kk][0], qf[kk][1], qf[kk][2], qf[kk][3],
                 sptr(Qs + row * 64 + ((ch ^ (row & 7)) << 3)));
        }
    }

    float oacc[8][4];
#pragma unroll
    for (int j = 0; j < 8; j++)
#pragma unroll
        for (int i = 0; i < 4; i++) oacc[j][i] = 0.f;
    float m0 = -1e30f, m1 = -1e30f, l0 = 0.f, l1 = 0.f;

    const int kbase = z * (N_NODES / KSPLIT);
    for (int kt = 0; kt < (N_NODES / KSPLIT) / 64; kt++) {
        int k0g = kbase + kt * 64;
        __syncthreads();
        {
            int r = t >> 1, cb = (t & 1) * 4;
            const uint4* sk = (const uint4*)(qkvb + (size_t)(k0g + r) * 768 + 256 + head * 64);
            const uint4* sv = (const uint4*)(qkvb + (size_t)(k0g + r) * 768 + 512 + head * 64);
            uint4* dk = (uint4*)(Ks + r * 64);
            uint4* dv = (uint4*)(Vs + r * 64);
#pragma unroll
            for (int i = 0; i < 4; i++) {
                int c = cb + i;
                dk[c ^ (r & 7)] = sk[c];
                dv[c ^ (r & 7)] = sv[c];
            }
        }
        __syncthreads();

        // S = Q @ K^T : 8 n-tiles (keys), 4 k-steps (hd)
        float sacc[8][4];
#pragma unroll
        for (int j = 0; j < 8; j++)
#pragma unroll
            for (int i = 0; i < 4; i++) sacc[j][i] = 0.f;
#pragma unroll
        for (int kk = 0; kk < 4; kk++) {
#pragma unroll
            for (int jp = 0; jp < 4; jp++) {
                unsigned b0, b1, b2, b3;
                int keyrow = 16 * jp + (mq >> 1) * 8 + r_in;
                int ch = 2 * kk + (mq & 1);
                ldm4(b0, b1, b2, b3, sptr(Ks + keyrow * 64 + ((ch ^ (keyrow & 7)) << 3)));
                unsigned bb0[2] = {b0, b1}, bb1[2] = {b2, b3};
                mma_bf16(sacc[2 * jp], qf[kk], bb0);
                mma_bf16(sacc[2 * jp + 1], qf[kk], bb1);
            }
        }

        // online softmax (rows r and r+8; quad lanes share a row)
        float tm0 = -1e30f, tm1 = -1e30f;
#pragma unroll
        for (int j = 0; j < 8; j++) {
            tm0 = fmaxf(tm0, fmaxf(sacc[j][0], sacc[j][1]));
            tm1 = fmaxf(tm1, fmaxf(sacc[j][2], sacc[j][3]));
        }
#pragma unroll
        for (int o = 1; o < 4; o <<= 1) {
            tm0 = fmaxf(tm0, __shfl_xor_sync(0xffffffffu, tm0, o));
            tm1 = fmaxf(tm1, __shfl_xor_sync(0xffffffffu, tm1, o));
        }
        float mn0 = fmaxf(m0, tm0), mn1 = fmaxf(m1, tm1);
        float c0 = __expf(m0 - mn0), c1 = __expf(m1 - mn1);
        l0 *= c0; l1 *= c1;
#pragma unroll
        for (int j = 0; j < 8; j++) {
            oacc[j][0] *= c0; oacc[j][1] *= c0;
            oacc[j][2] *= c1; oacc[j][3] *= c1;
        }
        unsigned pb[8][2];
#pragma unroll
        for (int j = 0; j < 8; j++) {
            float p0 = __expf(sacc[j][0] - mn0), p1 = __expf(sacc[j][1] - mn0);
            float p2 = __expf(sacc[j][2] - mn1), p3 = __expf(sacc[j][3] - mn1);
            l0 += p0 + p1; l1 += p2 + p3;
            pb[j][0] = packbf(p0, p1);
            pb[j][1] = packbf(p2, p3);
        }
        m0 = mn0; m1 = mn1;

        // O += P @ V : 4 k-steps (keys), 8 n-tiles (hd)
#pragma unroll
        for (int kk = 0; kk < 4; kk++) {
            unsigned a[4] = {pb[2 * kk][0], pb[2 * kk][1], pb[2 * kk + 1][0], pb[2 * kk + 1][1]};
#pragma unroll
            for (int jp = 0; jp < 4; jp++) {
                unsigned b0, b1, b2, b3;
                int keyrow = 16 * kk + (mq & 1) * 8 + r_in;
                int ch = 2 * jp + (mq >> 1);
                ldm4t(b0, b1, b2, b3, sptr(Vs + keyrow * 64 + ((ch ^ (keyrow & 7)) << 3)));
                unsigned bb0[2] = {b0, b1}, bb1[2] = {b2, b3};
                mma_bf16(oacc[2 * jp], a, bb0);
                mma_bf16(oacc[2 * jp + 1], a, bb1);
            }
        }
    }

    // reduce l across quad
#pragma unroll
    for (int o = 1; o < 4; o <<= 1) {
        l0 += __shfl_xor_sync(0xffffffffu, l0, o);
        l1 += __shfl_xor_sync(0xffffffffu, l1, o);
    }
    int r = lane >> 2, cc = lane & 3;
    int row0 = q0 + 16 * w + r;
    int idx0 = (head * KSPLIT + z) * N_NODES + row0;
    int idx1 = idx0 + 8;
    float2* p0 = (float2*)(g_pacc + (size_t)idx0 * HD);
    float2* p1 = (float2*)(g_pacc + (size_t)idx1 * HD);
#pragma unroll
    for (int j = 0; j < 8; j++) {
        p0[4 * j + cc] = make_float2(oacc[j][0], oacc[j][1]);
        p1[4 * j + cc] = make_float2(oacc[j][2], oacc[j][3]);
    }
    if (cc == 0) {
        g_pm[idx0] = m0; g_pl[idx0] = l0;
        g_pm[idx1] = m1; g_pl[idx1] = l1;
    }
}

__global__ void k_merge(float* __restrict__ ctx) {
    int gid = blockIdx.x * blockDim.x + threadIdx.x;  // NHEAD*N*HD
    int d = gid & (HD - 1);
    int n = (gid >> 6) & (N_NODES - 1);
    int head = gid >> 18;
    float M = -1e30f;
#pragma unroll
    for (int z = 0; z < KSPLIT; z++)
        M = fmaxf(M, g_pm[(head * KSPLIT + z) * N_NODES + n]);
    float num = 0.f, den = 0.f;
#pragma unroll
    for (int z = 0; z < KSPLIT; z++) {
        int idx = (head * KSPLIT + z) * N_NODES + n;
        float wz = __expf(g_pm[idx] - M);
        num += wz * g_pacc[(size_t)idx * HD + d];
        den += wz * g_pl[idx];
    }
    ctx[n * H + head * HD + d] = num / den;
}

// out = (res ? res : 0) + LayerNorm(a + b) * g + beta
__global__ void k_ln(const float* __restrict__ a, const float* __restrict__ bb,
                     const float* __restrict__ g, const float* __restrict__ beta,
                     const float* __restrict__ res, float* __restrict__ out) {
    int n = blockIdx.x, t = threadIdx.x;  // 256
    float v = a[n * H + t] + bb[n * H + t];
    __shared__ float red[8];
    float s = v;
#pragma unroll
    for (int o = 16; o; o >>= 1) s += __shfl_xor_sync(0xffffffffu, s, o);
    if ((t & 31) == 0) red[t >> 5] = s;
    __syncthreads();
    float tot = 0.f;
#pragma unroll
    for (int i = 0; i < 8; i++) tot += red[i];
    float mean = tot * (1.f / H);
    float d = v - mean;
    float s2 = d * d;
#pragma unroll
    for (int o = 16; o; o >>= 1) s2 += __shfl_xor_sync(0xffffffffu, s2, o);
    __syncthreads();
    if ((t & 31) == 0) red[t >> 5] = s2;
    __syncthreads();
    float tot2 = 0.f;
#pragma unroll
    for (int i = 0; i < 8; i++) tot2 += red[i];
    float var = tot2 * (1.f / H);
    float o_ = d * rsqrtf(var + EPS) * g[t] + beta[t];
    if (res) o_ += res[n * H + t];
    out[n * H + t] = o_;
}

// classifier head + log_softmax (warp per row)
__global__ void k_cls(const float* __restrict__ xf, const float* __restrict__ W,
                      const float* __restrict__ b, float* __restrict__ out) {
    int n = blockIdx.x;
    int lane = threadIdx.x;  // 32
    float acc = -1e30f;
    if (lane < NCLS) {
        const float* xr = xf + (size_t)n * H;
        float a = 0.f;
        for (int k = 0; k < H; k++) a += xr[k] * W[k * NCLS + lane];
        acc = a + b[lane];
    }
    float mx = acc;
#pragma unroll
    for (int o = 8; o; o >>= 1) mx = fmaxf(mx, __shfl_xor_sync(0xffffffffu, mx, o, 16));
    float e = (lane < NCLS) ? __expf(acc - mx) : 0.f;
    float se = e;
#pragma unroll
    for (int o = 8; o; o >>= 1) se += __shfl_xor_sync(0xffffffffu, se, o, 16);
    if (lane < NCLS) out[n * NCLS + lane] = acc - mx - logf(se);
}

// decoder second layer + sigmoid (warp per row)
__global__ void k_d2(const float* __restrict__ d1, const float* __restrict__ W,
                     const float* __restrict__ b, float* __restrict__ out) {
    int n = blockIdx.x;
    int lane = threadIdx.x;
    const float* xr = d1 + (size_t)n * (2 * H);
    float a0 = 0.f, a1 = 0.f, a2 = 0.f;
    for (int k = lane; k < 2 * H; k += 32) {
        float xv = xr[k];
        a0 += xv * W[k * 3 + 0];
        a1 += xv * W[k * 3 + 1];
        a2 += xv * W[k * 3 + 2];
    }
#pragma unroll
    for (int o = 16; o; o >>= 1) {
        a0 += __shfl_xor_sync(0xffffffffu, a0, o);
        a1 += __shfl_xor_sync(0xffffffffu, a1, o);
        a2 += __shfl_xor_sync(0xffffffffu, a2, o);
    }
    if (lane == 0) {
        out[n * 3 + 0] = 1.f / (1.f + __expf(-(a0 + b[0])));
        out[n * 3 + 1] = 1.f / (1.f + __expf(-(a1 + b[1])));
        out[n * 3 + 2] = 1.f / (1.f + __expf(-(a2 + b[2])));
    }
}

// ---------------- launch ----------------
static float* symf(const void* sym) {
    void* p = nullptr;
    cudaGetSymbolAddress(&p, sym);
    return (float*)p;
}

extern "C" void kernel_launch(void* const* d_in, const int* in_sizes, int n_in,
                              void* d_out, int out_size) {
    const float* x        = (const float*)d_in[0];
    const int*   ei       = (const int*)d_in[1];
    const float* ea       = (const float*)d_in[2];
    const float* W_gcn1   = (const float*)d_in[3];
    const float* b_gcn1   = (const float*)d_in[4];
    const float* W_gcn2   = (const float*)d_in[5];
    const float* b_gcn2   = (const float*)d_in[6];
    const float* in_proj_w  = (const float*)d_in[7];
    const float* in_proj_b  = (const float*)d_in[8];
    const float* out_proj_w = (const float*)d_in[9];
    const float* out_proj_b = (const float*)d_in[10];
    const float* ln1_g    = (const float*)d_in[11];
    const float* ln1_b    = (const float*)d_in[12];
    const float* ffn_w1   = (const float*)d_in[13];
    const float* ffn_b1   = (const float*)d_in[14];
    const float* ffn_w2   = (const float*)d_in[15];
    const float* ffn_b2   = (const float*)d_in[16];
    const float* ln2_g    = (const float*)d_in[17];
    const float* ln2_b    = (const float*)d_in[18];
    const float* W_cls    = (const float*)d_in[19];
    const float* b_cls    = (const float*)d_in[20];
    const float* W_d1     = (const float*)d_in[21];
    const float* b_d1     = (const float*)d_in[22];
    const float* W_d2     = (const float*)d_in[23];
    const float* b_d2     = (const float*)d_in[24];

    float* out_cls  = (float*)d_out;
    float* out_reco = out_cls + (size_t)N_NODES * NCLS;

    float* p_h   = symf(g_h);
    float* p_g1  = symf(g_g1);
    float* p_xl  = symf(g_xl);
    float* p_qkv = symf(g_qkv);
    float* p_ctx = symf(g_ctx);
    float* p_x1  = symf(g_x1);
    float* p_ffn = symf(g_ffn);
    float* p_f2  = symf(g_f2);
    float* p_xf  = symf(g_xf);
    float* p_d1  = symf(g_d1);
    __nv_bfloat16* p_qkvb;
    { void* pp = nullptr; cudaGetSymbolAddress(&pp, g_qkvb); p_qkvb = (__nv_bfloat16*)pp; }

    // graph structure
    k_zero<<<N_NODES / 256, 256>>>();
    k_deg<<<N_EDGES / 256, 256>>>(ei, ea);
    k_dinv<<<N_NODES / 256, 256>>>();
    k_scan<<<1, 1024>>>();
    k_fill<<<N_EDGES / 256, 256>>>(ei);

    // GCN layer 1: h = x @ W1 ; gather ; +b ; relu
    k_gemm<false, 0><<<dim3(H / 64, N_NODES / 64), 256>>>(x, W_gcn1, nullptr, p_h,
                                                          N_NODES, H, IN_CH);
    k_gather<<<N_NODES, H>>>(p_h, ei, ea, b_gcn1, p_g1, 1);

    // GCN layer 2
    k_gemm<false, 0><<<dim3(H / 64, N_NODES / 64), 256>>>(p_g1, W_gcn2, nullptr, p_h,
                                                          N_NODES, H, H);
    k_gather<<<N_NODES, H>>>(p_h, ei, ea, b_gcn2, p_xl, 0);

    // QKV projection (B transposed)
    k_gemm<true, 0><<<dim3(3 * H / 64, N_NODES / 64), 256>>>(p_xl, in_proj_w, in_proj_b,
                                                             p_qkv, N_NODES, 3 * H, H);

    // attention (bf16 tensor-core flash)
    k_cvt_qkv<<<(N_NODES * 3 * H) / 256, 256>>>(p_qkv, p_qkvb);
    k_attn_mma<<<dim3(N_NODES / 64, NHEAD, KSPLIT), 128>>>(p_qkvb);
    k_merge<<<(NHEAD * N_NODES * HD) / 256, 256>>>(p_ctx);

    // out projection (B transposed)
    k_gemm<true, 0><<<dim3(H / 64, N_NODES / 64), 256>>>(p_ctx, out_proj_w, out_proj_b,
                                                         p_h, N_NODES, H, H);

    // x1 = LN(x_local + attn_out)
    k_ln<<<N_NODES, H>>>(p_xl, p_h, ln1_g, ln1_b, nullptr, p_x1);

    // FFN
    k_gemm<false, 1><<<dim3(4 * H / 64, N_NODES / 64), 256>>>(p_x1, ffn_w1, ffn_b1,
                                                              p_ffn, N_NODES, 4 * H, H);
    k_gemm<false, 0><<<dim3(H / 64, N_NODES / 64), 256>>>(p_ffn, ffn_w2, ffn_b2,
                                                          p_f2, N_NODES, H, 4 * H);

    // x_final = x_local + LN(x1 + ffn_out)
    k_ln<<<N_NODES, H>>>(p_x1, p_f2, ln2_g, ln2_b, p_xl, p_xf);

    // heads
    k_cls<<<N_NODES, 32>>>(p_xf, W_cls, b_cls, out_cls);
    k_gemm<false, 1><<<dim3(2 * H / 64, N_NODES / 64), 256>>>(p_xf, W_d1, b_d1,
                                                              p_d1, N_NODES, 2 * H, H);
    k_d2<<<N_NODES, 32>>>(p_d1, W_d2, b_d2, out_reco);
}

// round 3
// speedup vs baseline: 3.2699x; 1.3910x over previous
#include <cuda_runtime.h>
#include <cuda_bf16.h>
#include <math.h>

#define N_NODES 4096
#define N_EDGES 131072
#define IN_CH   128
#define H       256
#define NCLS    16
#define NHEAD   4
#define HD      64
#define KSPLIT  2
#define EPS     1e-5f

// ---------------- device scratch (static, no allocs) ----------------
__device__ float g_deg[N_NODES];
__device__ float g_dinv[N_NODES];
__device__ int   g_cnt[N_NODES];
__device__ int   g_rowptr[N_NODES + 1];
__device__ int   g_cursor[N_NODES];
__device__ int   g_eidx[N_EDGES];

__device__ __align__(16) float g_h   [N_NODES * H];       // gemm scratch
__device__ __align__(16) float g_g1  [N_NODES * H];       // gcn1 out (relu)
__device__ __align__(16) float g_xl  [N_NODES * H];       // x_local
__device__ __align__(16) __nv_bfloat16 g_qkvb[N_NODES * 3 * H];  // bf16 QKV (Q pre-scaled)
__device__ __align__(16) float g_ctx [N_NODES * H];
__device__ __align__(16) float g_x1  [N_NODES * H];       // after ln1
__device__ __align__(16) float g_ffn [N_NODES * 4 * H];
__device__ __align__(16) float g_f2  [N_NODES * H];
__device__ __align__(16) float g_xf  [N_NODES * H];       // x_final
__device__ __align__(16) float g_d1  [N_NODES * 2 * H];
__device__ __align__(16) float g_pacc[NHEAD * KSPLIT * N_NODES * HD];
__device__ float g_pm[NHEAD * KSPLIT * N_NODES];
__device__ float g_pl[NHEAD * KSPLIT * N_NODES];

// ---------------- mma helpers ----------------
__device__ __forceinline__ unsigned sptr(const void* p) {
    return (unsigned)__cvta_generic_to_shared(p);
}
__device__ __forceinline__ void ldm4(unsigned& r0, unsigned& r1, unsigned& r2, unsigned& r3,
                                     unsigned addr) {
    asm volatile("ldmatrix.sync.aligned.m8n8.x4.shared.b16 {%0,%1,%2,%3},[%4];"
                 : "=r"(r0), "=r"(r1), "=r"(r2), "=r"(r3) : "r"(addr));
}
__device__ __forceinline__ void ldm4t(unsigned& r0, unsigned& r1, unsigned& r2, unsigned& r3,
                                      unsigned addr) {
    asm volatile("ldmatrix.sync.aligned.m8n8.x4.trans.shared.b16 {%0,%1,%2,%3},[%4];"
                 : "=r"(r0), "=r"(r1), "=r"(r2), "=r"(r3) : "r"(addr));
}
__device__ __forceinline__ void mma_bf16(float* d, const unsigned* a, const unsigned* b) {
    asm volatile("mma.sync.aligned.m16n8k16.row.col.f32.bf16.bf16.f32 "
                 "{%0,%1,%2,%3},{%4,%5,%6,%7},{%8,%9},{%0,%1,%2,%3};"
                 : "+f"(d[0]), "+f"(d[1]), "+f"(d[2]), "+f"(d[3])
                 : "r"(a[0]), "r"(a[1]), "r"(a[2]), "r"(a[3]), "r"(b[0]), "r"(b[1]));
}
__device__ __forceinline__ void mma_tf32(float* d, const unsigned* a, const unsigned* b) {
    asm volatile("mma.sync.aligned.m16n8k8.row.col.f32.tf32.tf32.f32 "
                 "{%0,%1,%2,%3},{%4,%5,%6,%7},{%8,%9},{%0,%1,%2,%3};"
                 : "+f"(d[0]), "+f"(d[1]), "+f"(d[2]), "+f"(d[3])
                 : "r"(a[0]), "r"(a[1]), "r"(a[2]), "r"(a[3]), "r"(b[0]), "r"(b[1]));
}
__device__ __forceinline__ unsigned packbf(float lo, float hi) {
    unsigned r;
    asm("cvt.rn.bf16x2.f32 %0, %1, %2;" : "=r"(r) : "f"(hi), "f"(lo));
    return r;
}
__device__ __forceinline__ unsigned to_tf32(float f) {
    unsigned r;
    asm("cvt.rna.tf32.f32 %0, %1;" : "=r"(r) : "f"(f));
    return r;
}

// ---------------- small kernels ----------------
__global__ void k_zero() {
    int i = blockIdx.x * blockDim.x + threadIdx.x;
    if (i < N_NODES) { g_deg[i] = 0.f; g_cnt[i] = 0; }
}

__global__ void k_deg(const int* __restrict__ ei, const float* __restrict__ ew) {
    int e = blockIdx.x * blockDim.x + threadIdx.x;
    if (e < N_EDGES) {
        int d = ei[N_EDGES + e];
        atomicAdd(&g_deg[d], ew[e]);
        atomicAdd(&g_cnt[d], 1);
    }
}

__global__ void k_dinv() {
    int i = blockIdx.x * blockDim.x + threadIdx.x;
    if (i < N_NODES) g_dinv[i] = rsqrtf(g_deg[i] + 1.0f);  // self-loop weight 1
}

// exclusive scan of g_cnt -> g_rowptr / g_cursor (single block, 1024 threads)
__global__ void k_scan() {
    __shared__ int wsum[32];
    int t = threadIdx.x;
    int base = t * 4;
    int v[4];
#pragma unroll
    for (int i = 0; i < 4; i++) v[i] = g_cnt[base + i];
    int tot = v[0] + v[1] + v[2] + v[3];
    int lane = t & 31, w = t >> 5;
    int x = tot;
#pragma unroll
    for (int o = 1; o < 32; o <<= 1) {
        int y = __shfl_up_sync(0xffffffffu, x, o);
        if (lane >= o) x += y;
    }
    if (lane == 31) wsum[w] = x;
    __syncthreads();
    if (w == 0) {
        int y = wsum[lane];
#pragma unroll
        for (int o = 1; o < 32; o <<= 1) {
            int z = __shfl_up_sync(0xffffffffu, y, o);
            if (lane >= o) y += z;
        }
        wsum[lane] = y;
    }
    __syncthreads();
    int wbase = (w > 0) ? wsum[w - 1] : 0;
    int run = wbase + x - tot;   // exclusive prefix
#pragma unroll
    for (int i = 0; i < 4; i++) {
        g_rowptr[base + i] = run;
        g_cursor[base + i] = run;
        run += v[i];
    }
    if (t == 1023) g_rowptr[N_NODES] = run;
}

__global__ void k_fill(const int* __restrict__ ei) {
    int e = blockIdx.x * blockDim.x + threadIdx.x;
    if (e < N_EDGES) {
        int d = ei[N_EDGES + e];
        int p = atomicAdd(&g_cursor[d], 1);
        g_eidx[p] = e;
    }
}

// GCN aggregation
__global__ void k_gather(const float* __restrict__ h, const int* __restrict__ ei,
                         const float* __restrict__ ew, const float* __restrict__ bias,
                         float* __restrict__ out, int relu) {
    int n = blockIdx.x;
    int c = threadIdx.x;  // 256
    int beg = g_rowptr[n], end = g_rowptr[n + 1];
    float dn = g_dinv[n];
    float acc = dn * dn * h[n * H + c];
    __shared__ int   ssrc[64];
    __shared__ float scoef[64];
    for (int b0 = beg; b0 < end; b0 += 64) {
        int cnt = min(64, end - b0);
        if (c < cnt) {
            int e = g_eidx[b0 + c];
            int s = ei[e];
            ssrc[c] = s;
            scoef[c] = g_dinv[s] * ew[e] * dn;
        }
        __syncthreads();
        for (int i = 0; i < cnt; i++)
            acc += scoef[i] * h[ssrc[i] * H + c];
        __syncthreads();
    }
    float v = acc + bias[c];
    out[n * H + c] = relu ? fmaxf(v, 0.f) : v;
}

// ---------------- tf32 tensor-core GEMM ----------------
// C[M,N] = A[M,K] @ B (+bias). BT: B is [N,K] (C = A@B^T) else [K,N].
// MODE: 0 = fp32 out, 1 = fp32 out + relu, 2 = bf16 out with QKV scaling (cols<H *= 0.125)
// CTA tile 128x64, 8 warps (4m x 2n), each warp 32x32. K multiple of 16.
template <bool BT, int MODE>
__global__ void __launch_bounds__(256) k_gemm_tf(const float* __restrict__ A,
                                                 const float* __restrict__ B,
                                                 const float* __restrict__ bias,
                                                 void* __restrict__ Cv,
                                                 int M, int Nn, int K) {
    __shared__ unsigned As[16][136];  // [k][m], pad 8 -> conflict-free frags
    __shared__ unsigned Bs[16][72];   // [k][n], pad 8
    const int tid = threadIdx.x;
    const int wid = tid >> 5, lane = tid & 31;
    const int wm = wid & 3, wn = wid >> 2;
    const int m0 = blockIdx.y * 128, n0 = blockIdx.x * 64;
    const int r = lane >> 2, c = lane & 3;

    float acc[2][4][4];
#pragma unroll
    for (int mt = 0; mt < 2; mt++)
#pragma unroll
        for (int jn = 0; jn < 4; jn++)
#pragma unroll
            for (int i = 0; i < 4; i++) acc[mt][jn][i] = 0.f;

    for (int k0 = 0; k0 < K; k0 += 16) {
        // stage A: 128 rows x 16 k = 512 float4
#pragma unroll
        for (int i = 0; i < 2; i++) {
            int idx = tid + i * 256;
            int row = idx >> 2, kq = idx & 3;
            float4 v = *(const float4*)(A + (size_t)(m0 + row) * K + k0 + 4 * kq);
            As[4 * kq + 0][row] = to_tf32(v.x);
            As[4 * kq + 1][row] = to_tf32(v.y);
            As[4 * kq + 2][row] = to_tf32(v.z);
            As[4 * kq + 3][row] = to_tf32(v.w);
        }
        // stage B
        if (BT) {
            int n = tid >> 2, kq = tid & 3;
            float4 v = *(const float4*)(B + (size_t)(n0 + n) * K + k0 + 4 * kq);
            Bs[4 * kq + 0][n] = to_tf32(v.x);
            Bs[4 * kq + 1][n] = to_tf32(v.y);
            Bs[4 * kq + 2][n] = to_tf32(v.z);
            Bs[4 * kq + 3][n] = to_tf32(v.w);
        } else {
            int kk = tid >> 4, nq = tid & 15;
            float4 v = *(const float4*)(B + (size_t)(k0 + kk) * Nn + n0 + 4 * nq);
            Bs[kk][4 * nq + 0] = to_tf32(v.x);
            Bs[kk][4 * nq + 1] = to_tf32(v.y);
            Bs[kk][4 * nq + 2] = to_tf32(v.z);
            Bs[kk][4 * nq + 3] = to_tf32(v.w);
        }
        __syncthreads();

#pragma unroll
        for (int ks = 0; ks < 16; ks += 8) {
            unsigned a[2][4], b[4][2];
#pragma unroll
            for (int mt = 0; mt < 2; mt++) {
                int row = wm * 32 + mt * 16 + r;
                a[mt][0] = As[ks + c][row];
                a[mt][1] = As[ks + c][row + 8];
                a[mt][2] = As[ks + 4 + c][row];
                a[mt][3] = As[ks + 4 + c][row + 8];
            }
#pragma unroll
            for (int jn = 0; jn < 4; jn++) {
                int col = wn * 32 + jn * 8 + r;
                b[jn][0] = Bs[ks + c][col];
                b[jn][1] = Bs[ks + 4 + c][col];
            }
#pragma unroll
            for (int mt = 0; mt < 2; mt++)
#pragma unroll
                for (int jn = 0; jn < 4; jn++)
                    mma_tf32(acc[mt][jn], a[mt], b[jn]);
        }
        __syncthreads();
    }

    // epilogue
#pragma unroll
    for (int mt = 0; mt < 2; mt++) {
        int mrow0 = m0 + wm * 32 + mt * 16 + r;
#pragma unroll
        for (int jn = 0; jn < 4; jn++) {
            int col = n0 + wn * 32 + jn * 8 + 2 * c;
            float bz0 = bias ? bias[col] : 0.f;
            float bz1 = bias ? bias[col + 1] : 0.f;
            float v00 = acc[mt][jn][0] + bz0, v01 = acc[mt][jn][1] + bz1;
            float v10 = acc[mt][jn][2] + bz0, v11 = acc[mt][jn][3] + bz1;
            if (MODE == 1) {
                v00 = fmaxf(v00, 0.f); v01 = fmaxf(v01, 0.f);
                v10 = fmaxf(v10, 0.f); v11 = fmaxf(v11, 0.f);
            }
            if (MODE == 2) {
                float s = (col < H) ? 0.125f : 1.0f;  // Q pre-scale; col pairs don't straddle
                __nv_bfloat16* C = (__nv_bfloat16*)Cv;
                *(unsigned*)(C + (size_t)mrow0 * Nn + col) = packbf(v00 * s, v01 * s);
                *(unsigned*)(C + (size_t)(mrow0 + 8) * Nn + col) = packbf(v10 * s, v11 * s);
            } else {
                float* C = (float*)Cv;
                *(float2*)(C + (size_t)mrow0 * Nn + col) = make_float2(v00, v01);
                *(float2*)(C + (size_t)(mrow0 + 8) * Nn + col) = make_float2(v10, v11);
            }
        }
    }
}

// ---------------- attention: bf16 mma flash, 64q x 64k tiles ----------------
__global__ void __launch_bounds__(128) k_attn_mma(const __nv_bfloat16* __restrict__ qkvb) {
    __shared__ __align__(16) __nv_bfloat16 Qs[64 * 64];
    __shared__ __align__(16) __nv_bfloat16 Ks[64 * 64];
    __shared__ __align__(16) __nv_bfloat16 Vs[64 * 64];
    const int head = blockIdx.y, z = blockIdx.z;
    const int q0 = blockIdx.x * 64;
    const int t = threadIdx.x, w = t >> 5, lane = t & 31;
    const int r_in = lane & 7, mq = lane >> 3;

    // stage Q tile (rows q0..q0+63, head slice), XOR-swizzled per row
    {
        int r = t >> 1, cb = (t & 1) * 4;
        const uint4* src = (const uint4*)(qkvb + (size_t)(q0 + r) * 768 + head * 64);
        uint4* dst = (uint4*)(Qs + r * 64);
#pragma unroll
        for (int i = 0; i < 4; i++) { int c = cb + i; dst[c ^ (r & 7)] = src[c]; }
    }
    __syncthreads();

    // Q A-fragments: warp rows 16w..16w+15, 4 k16 steps over HD
    unsigned qf[4][4];
    {
        int row = 16 * w + (mq & 1) * 8 + r_in;
#pragma unroll
        for (int kk = 0; kk < 4; kk++) {
            int ch = 2 * kk + (mq >> 1);
            ldm4(qf[kk][0], qf[kk][1], qf[kk][2], qf[kk][3],
                 sptr(Qs + row * 64 + ((ch ^ (row & 7)) << 3)));
        }
    }

    float oacc[8][4];
#pragma unroll
    for (int j = 0; j < 8; j++)
#pragma unroll
        for (int i = 0; i < 4; i++) oacc[j][i] = 0.f;
    float m0 = -1e30f, m1 = -1e30f, l0 = 0.f, l1 = 0.f;

    const int kbase = z * (N_NODES / KSPLIT);
    for (int kt = 0; kt < (N_NODES / KSPLIT) / 64; kt++) {
        int k0g = kbase + kt * 64;
        __syncthreads();
        {
            int r = t >> 1, cb = (t & 1) * 4;
            const uint4* sk = (const uint4*)(qkvb + (size_t)(k0g + r) * 768 + 256 + head * 64);
            const uint4* sv = (const uint4*)(qkvb + (size_t)(k0g + r) * 768 + 512 + head * 64);
            uint4* dk = (uint4*)(Ks + r * 64);
            uint4* dv = (uint4*)(Vs + r * 64);
#pragma unroll
            for (int i = 0; i < 4; i++) {
                int c = cb + i;
                dk[c ^ (r & 7)] = sk[c];
                dv[c ^ (r & 7)] = sv[c];
            }
        }
        __syncthreads();

        // S = Q @ K^T : 8 n-tiles (keys), 4 k-steps (hd)
        float sacc[8][4];
#pragma unroll
        for (int j = 0; j < 8; j++)
#pragma unroll
            for (int i = 0; i < 4; i++) sacc[j][i] = 0.f;
#pragma unroll
        for (int kk = 0; kk < 4; kk++) {
#pragma unroll
            for (int jp = 0; jp < 4; jp++) {
                unsigned b0, b1, b2, b3;
                int keyrow = 16 * jp + (mq >> 1) * 8 + r_in;
                int ch = 2 * kk + (mq & 1);
                ldm4(b0, b1, b2, b3, sptr(Ks + keyrow * 64 + ((ch ^ (keyrow & 7)) << 3)));
                unsigned bb0[2] = {b0, b1}, bb1[2] = {b2, b3};
                mma_bf16(sacc[2 * jp], qf[kk], bb0);
                mma_bf16(sacc[2 * jp + 1], qf[kk], bb1);
            }
        }

        // online softmax (rows r and r+8; quad lanes share a row)
        float tm0 = -1e30f, tm1 = -1e30f;
#pragma unroll
        for (int j = 0; j < 8; j++) {
            tm0 = fmaxf(tm0, fmaxf(sacc[j][0], sacc[j][1]));
            tm1 = fmaxf(tm1, fmaxf(sacc[j][2], sacc[j][3]));
        }
#pragma unroll
        for (int o = 1; o < 4; o <<= 1) {
            tm0 = fmaxf(tm0, __shfl_xor_sync(0xffffffffu, tm0, o));
            tm1 = fmaxf(tm1, __shfl_xor_sync(0xffffffffu, tm1, o));
        }
        float mn0 = fmaxf(m0, tm0), mn1 = fmaxf(m1, tm1);
        float c0 = __expf(m0 - mn0), c1 = __expf(m1 - mn1);
        l0 *= c0; l1 *= c1;
#pragma unroll
        for (int j = 0; j < 8; j++) {
            oacc[j][0] *= c0; oacc[j][1] *= c0;
            oacc[j][2] *= c1; oacc[j][3] *= c1;
        }
        unsigned pb[8][2];
#pragma unroll
        for (int j = 0; j < 8; j++) {
            float p0 = __expf(sacc[j][0] - mn0), p1 = __expf(sacc[j][1] - mn0);
            float p2 = __expf(sacc[j][2] - mn1), p3 = __expf(sacc[j][3] - mn1);
            l0 += p0 + p1; l1 += p2 + p3;
            pb[j][0] = packbf(p0, p1);
            pb[j][1] = packbf(p2, p3);
        }
        m0 = mn0; m1 = mn1;

        // O += P @ V : 4 k-steps (keys), 8 n-tiles (hd)
#pragma unroll
        for (int kk = 0; kk < 4; kk++) {
            unsigned a[4] = {pb[2 * kk][0], pb[2 * kk][1], pb[2 * kk + 1][0], pb[2 * kk + 1][1]};
#pragma unroll
            for (int jp = 0; jp < 4; jp++) {
                unsigned b0, b1, b2, b3;
                int keyrow = 16 * kk + (mq & 1) * 8 + r_in;
                int ch = 2 * jp + (mq >> 1);
                ldm4t(b0, b1, b2, b3, sptr(Vs + keyrow * 64 + ((ch ^ (keyrow & 7)) << 3)));
                unsigned bb0[2] = {b0, b1}, bb1[2] = {b2, b3};
                mma_bf16(oacc[2 * jp], a, bb0);
                mma_bf16(oacc[2 * jp + 1], a, bb1);
            }
        }
    }

    // reduce l across quad
#pragma unroll
    for (int o = 1; o < 4; o <<= 1) {
        l0 += __shfl_xor_sync(0xffffffffu, l0, o);
        l1 += __shfl_xor_sync(0xffffffffu, l1, o);
    }
    int r = lane >> 2, cc = lane & 3;
    int row0 = q0 + 16 * w + r;
    int idx0 = (head * KSPLIT + z) * N_NODES + row0;
    int idx1 = idx0 + 8;
    float2* p0 = (float2*)(g_pacc + (size_t)idx0 * HD);
    float2* p1 = (float2*)(g_pacc + (size_t)idx1 * HD);
#pragma unroll
    for (int j = 0; j < 8; j++) {
        p0[4 * j + cc] = make_float2(oacc[j][0], oacc[j][1]);
        p1[4 * j + cc] = make_float2(oacc[j][2], oacc[j][3]);
    }
    if (cc == 0) {
        g_pm[idx0] = m0; g_pl[idx0] = l0;
        g_pm[idx1] = m1; g_pl[idx1] = l1;
    }
}

__global__ void k_merge(float* __restrict__ ctx) {
    int gid = blockIdx.x * blockDim.x + threadIdx.x;  // NHEAD*N*HD
    int d = gid & (HD - 1);
    int n = (gid >> 6) & (N_NODES - 1);
    int head = gid >> 18;
    float M = -1e30f;
#pragma unroll
    for (int z = 0; z < KSPLIT; z++)
        M = fmaxf(M, g_pm[(head * KSPLIT + z) * N_NODES + n]);
    float num = 0.f, den = 0.f;
#pragma unroll
    for (int z = 0; z < KSPLIT; z++) {
        int idx = (head * KSPLIT + z) * N_NODES + n;
        float wz = __expf(g_pm[idx] - M);
        num += wz * g_pacc[(size_t)idx * HD + d];
        den += wz * g_pl[idx];
    }
    ctx[n * H + head * HD + d] = num / den;
}

// out = (res ? res : 0) + LayerNorm(a + b) * g + beta
__global__ void k_ln(const float* __restrict__ a, const float* __restrict__ bb,
                     const float* __restrict__ g, const float* __restrict__ beta,
                     const float* __restrict__ res, float* __restrict__ out) {
    int n = blockIdx.x, t = threadIdx.x;  // 256
    float v = a[n * H + t] + bb[n * H + t];
    __shared__ float red[8];
    float s = v;
#pragma unroll
    for (int o = 16; o; o >>= 1) s += __shfl_xor_sync(0xffffffffu, s, o);
    if ((t & 31) == 0) red[t >> 5] = s;
    __syncthreads();
    float tot = 0.f;
#pragma unroll
    for (int i = 0; i < 8; i++) tot += red[i];
    float mean = tot * (1.f / H);
    float d = v - mean;
    float s2 = d * d;
#pragma unroll
    for (int o = 16; o; o >>= 1) s2 += __shfl_xor_sync(0xffffffffu, s2, o);
    __syncthreads();
    if ((t & 31) == 0) red[t >> 5] = s2;
    __syncthreads();
    float tot2 = 0.f;
#pragma unroll
    for (int i = 0; i < 8; i++) tot2 += red[i];
    float var = tot2 * (1.f / H);
    float o_ = d * rsqrtf(var + EPS) * g[t] + beta[t];
    if (res) o_ += res[n * H + t];
    out[n * H + t] = o_;
}

// classifier head + log_softmax (warp per row)
__global__ void k_cls(const float* __restrict__ xf, const float* __restrict__ W,
                      const float* __restrict__ b, float* __restrict__ out) {
    int n = blockIdx.x;
    int lane = threadIdx.x;  // 32
    float acc = -1e30f;
    if (lane < NCLS) {
        const float* xr = xf + (size_t)n * H;
        float a = 0.f;
        for (int k = 0; k < H; k++) a += xr[k] * W[k * NCLS + lane];
        acc = a + b[lane];
    }
    float mx = acc;
#pragma unroll
    for (int o = 8; o; o >>= 1) mx = fmaxf(mx, __shfl_xor_sync(0xffffffffu, mx, o, 16));
    float e = (lane < NCLS) ? __expf(acc - mx) : 0.f;
    float se = e;
#pragma unroll
    for (int o = 8; o; o >>= 1) se += __shfl_xor_sync(0xffffffffu, se, o, 16);
    if (lane < NCLS) out[n * NCLS + lane] = acc - mx - logf(se);
}

// decoder second layer + sigmoid (warp per row)
__global__ void k_d2(const float* __restrict__ d1, const float* __restrict__ W,
                     const float* __restrict__ b, float* __restrict__ out) {
    int n = blockIdx.x;
    int lane = threadIdx.x;
    const float* xr = d1 + (size_t)n * (2 * H);
    float a0 = 0.f, a1 = 0.f, a2 = 0.f;
    for (int k = lane; k < 2 * H; k += 32) {
        float xv = xr[k];
        a0 += xv * W[k * 3 + 0];
        a1 += xv * W[k * 3 + 1];
        a2 += xv * W[k * 3 + 2];
    }
#pragma unroll
    for (int o = 16; o; o >>= 1) {
        a0 += __shfl_xor_sync(0xffffffffu, a0, o);
        a1 += __shfl_xor_sync(0xffffffffu, a1, o);
        a2 += __shfl_xor_sync(0xffffffffu, a2, o);
    }
    if (lane == 0) {
        out[n * 3 + 0] = 1.f / (1.f + __expf(-(a0 + b[0])));
        out[n * 3 + 1] = 1.f / (1.f + __expf(-(a1 + b[1])));
        out[n * 3 + 2] = 1.f / (1.f + __expf(-(a2 + b[2])));
    }
}

// ---------------- launch ----------------
static float* symf(const void* sym) {
    void* p = nullptr;
    cudaGetSymbolAddress(&p, sym);
    return (float*)p;
}

extern "C" void kernel_launch(void* const* d_in, const int* in_sizes, int n_in,
                              void* d_out, int out_size) {
    const float* x        = (const float*)d_in[0];
    const int*   ei       = (const int*)d_in[1];
    const float* ea       = (const float*)d_in[2];
    const float* W_gcn1   = (const float*)d_in[3];
    const float* b_gcn1   = (const float*)d_in[4];
    const float* W_gcn2   = (const float*)d_in[5];
    const float* b_gcn2   = (const float*)d_in[6];
    const float* in_proj_w  = (const float*)d_in[7];
    const float* in_proj_b  = (const float*)d_in[8];
    const float* out_proj_w = (const float*)d_in[9];
    const float* out_proj_b = (const float*)d_in[10];
    const float* ln1_g    = (const float*)d_in[11];
    const float* ln1_b    = (const float*)d_in[12];
    const float* ffn_w1   = (const float*)d_in[13];
    const float* ffn_b1   = (const float*)d_in[14];
    const float* ffn_w2   = (const float*)d_in[15];
    const float* ffn_b2   = (const float*)d_in[16];
    const float* ln2_g    = (const float*)d_in[17];
    const float* ln2_b    = (const float*)d_in[18];
    const float* W_cls    = (const float*)d_in[19];
    const float* b_cls    = (const float*)d_in[20];
    const float* W_d1     = (const float*)d_in[21];
    const float* b_d1     = (const float*)d_in[22];
    const float* W_d2     = (const float*)d_in[23];
    const float* b_d2     = (const float*)d_in[24];

    float* out_cls  = (float*)d_out;
    float* out_reco = out_cls + (size_t)N_NODES * NCLS;

    float* p_h   = symf(g_h);
    float* p_g1  = symf(g_g1);
    float* p_xl  = symf(g_xl);
    float* p_ctx = symf(g_ctx);
    float* p_x1  = symf(g_x1);
    float* p_ffn = symf(g_ffn);
    float* p_f2  = symf(g_f2);
    float* p_xf  = symf(g_xf);
    float* p_d1  = symf(g_d1);
    __nv_bfloat16* p_qkvb;
    { void* pp = nullptr; cudaGetSymbolAddress(&pp, g_qkvb); p_qkvb = (__nv_bfloat16*)pp; }

    // graph structure
    k_zero<<<N_NODES / 256, 256>>>();
    k_deg<<<N_EDGES / 256, 256>>>(ei, ea);
    k_dinv<<<N_NODES / 256, 256>>>();
    k_scan<<<1, 1024>>>();
    k_fill<<<N_EDGES / 256, 256>>>(ei);

    // GCN layer 1: h = x @ W1 ; gather ; +b ; relu
    k_gemm_tf<false, 0><<<dim3(H / 64, N_NODES / 128), 256>>>(x, W_gcn1, nullptr, p_h,
                                                              N_NODES, H, IN_CH);
    k_gather<<<N_NODES, H>>>(p_h, ei, ea, b_gcn1, p_g1, 1);

    // GCN layer 2
    k_gemm_tf<false, 0><<<dim3(H / 64, N_NODES / 128), 256>>>(p_g1, W_gcn2, nullptr, p_h,
                                                              N_NODES, H, H);
    k_gather<<<N_NODES, H>>>(p_h, ei, ea, b_gcn2, p_xl, 0);

    // QKV projection (B transposed) -> bf16 qkv directly (Q pre-scaled)
    k_gemm_tf<true, 2><<<dim3(3 * H / 64, N_NODES / 128), 256>>>(p_xl, in_proj_w, in_proj_b,
                                                                 p_qkvb, N_NODES, 3 * H, H);

    // attention (bf16 tensor-core flash)
    k_attn_mma<<<dim3(N_NODES / 64, NHEAD, KSPLIT), 128>>>(p_qkvb);
    k_merge<<<(NHEAD * N_NODES * HD) / 256, 256>>>(p_ctx);

    // out projection (B transposed)
    k_gemm_tf<true, 0><<<dim3(H / 64, N_NODES / 128), 256>>>(p_ctx, out_proj_w, out_proj_b,
                                                             p_h, N_NODES, H, H);

    // x1 = LN(x_local + attn_out)
    k_ln<<<N_NODES, H>>>(p_xl, p_h, ln1_g, ln1_b, nullptr, p_x1);

    // FFN
    k_gemm_tf<false, 1><<<dim3(4 * H / 64, N_NODES / 128), 256>>>(p_x1, ffn_w1, ffn_b1,
                                                                  p_ffn, N_NODES, 4 * H, H);
    k_gemm_tf<false, 0><<<dim3(H / 64, N_NODES / 128), 256>>>(p_ffn, ffn_w2, ffn_b2,
                                                              p_f2, N_NODES, H, 4 * H);

    // x_final = x_local + LN(x1 + ffn_out)
    k_ln<<<N_NODES, H>>>(p_x1, p_f2, ln2_g, ln2_b, p_xl, p_xf);

    // heads
    k_cls<<<N_NODES, 32>>>(p_xf, W_cls, b_cls, out_cls);
    k_gemm_tf<false, 1><<<dim3(2 * H / 64, N_NODES / 128), 256>>>(p_xf, W_d1, b_d1,
                                                                  p_d1, N_NODES, 2 * H, H);
    k_d2<<<N_NODES, 32>>>(p_d1, W_d2, b_d2, out_reco);
}